// round 16
// baseline (speedup 1.0000x reference)
#include <cuda_runtime.h>

#define NBATCH   8
#define NANCH    9
#define DIMH     64
#define DIMW     64
#define HWSZ     (DIMH * DIMW)          // 4096
#define NPROP    (NANCH * HWSZ)         // 36864 candidates per batch
#define PRE_K    6000
#define POST_K   300
#define SORTN    8192                   // pow2 >= PRE_K (+ tie slack)
#define NMS_T    0.7f

// ---------------- global scratch (static, allocation-free) ----------------
__device__ unsigned long long g_keys[NBATCH * NPROP];   // (ord_score<<32)|~iref
__device__ float4             g_boxes[NBATCH * NPROP];  // decoded proposals

// ---------------- shared memory layout for kernel 2 ----------------
struct SmemLayout {
    float4             boxes[PRE_K];      // 96000 B
    unsigned long long skeys[SORTN];      // 65536 B
    unsigned int       hist[256];         //  1024 B
    int                counters[4];
    int                cur;
    unsigned char      alive[PRE_K];      //  6000 B
};                                        // ~168.6 KB total

// image_width / image_height may arrive as int32/int64 or float32; decode both.
__device__ __forceinline__ float decode_dim(unsigned u) {
    float f = __uint_as_float(u);
    return (f >= 1.0f && f <= 1.0e7f) ? f : (float)(int)u;
}

// =====================================================================
// Kernel 1: decode proposals + build sort keys (coalesced in (a, hw))
// =====================================================================
__global__ void __launch_bounds__(256)
proposal_decode_kernel(const float* __restrict__ scores,
                       const float* __restrict__ deltas,
                       const float* __restrict__ anchors,
                       const unsigned* __restrict__ pw,
                       const unsigned* __restrict__ ph)
{
    int g = blockIdx.x * blockDim.x + threadIdx.x;
    if (g >= NBATCH * NPROP) return;
    int b  = g / NPROP;
    int r  = g - b * NPROP;
    int a  = r / HWSZ;
    int hw = r - a * HWSZ;
    int h  = hw >> 6;
    int w  = hw & 63;

    float maxx = decode_dim(pw[0]) - 1.0f;   // 1023
    float maxy = decode_dim(ph[0]) - 1.0f;

    // fg score: scores[b, A+a, h, w]
    float sc = scores[(size_t)(b * (2 * NANCH) + NANCH + a) * HWSZ + hw];

    // deltas: bbox_deltas[b, 4a+k, h, w]
    const float* dp = deltas + (size_t)(b * (4 * NANCH) + 4 * a) * HWSZ + hw;
    float d0 = dp[0], d1 = dp[HWSZ], d2 = dp[2 * HWSZ], d3 = dp[3 * HWSZ];

    // shifted anchor
    float sx = (float)(w * 16), sy = (float)(h * 16);
    float a0 = __fadd_rn(anchors[a * 4 + 0], sx);
    float a1 = __fadd_rn(anchors[a * 4 + 1], sy);
    float a2 = __fadd_rn(anchors[a * 4 + 2], sx);
    float a3 = __fadd_rn(anchors[a * 4 + 3], sy);

    // explicit _rn ops: defeat FMA contraction / fast-math to match XLA
    float aw  = __fadd_rn(__fsub_rn(a2, a0), 1.0f);
    float ah  = __fadd_rn(__fsub_rn(a3, a1), 1.0f);
    float acx = __fadd_rn(a0, __fmul_rn(0.5f, aw));
    float acy = __fadd_rn(a1, __fmul_rn(0.5f, ah));
    float pcx = __fadd_rn(__fmul_rn(d0, aw), acx);
    float pcy = __fadd_rn(__fmul_rn(d1, ah), acy);
    float pwd = __fmul_rn(expf(d2), aw);
    float phd = __fmul_rn(expf(d3), ah);

    float x1 = fminf(fmaxf(__fsub_rn(pcx, __fmul_rn(0.5f, pwd)), 0.0f), maxx);
    float y1 = fminf(fmaxf(__fsub_rn(pcy, __fmul_rn(0.5f, phd)), 0.0f), maxy);
    float x2 = fminf(fmaxf(__fadd_rn(pcx, __fmul_rn(0.5f, pwd)), 0.0f), maxx);
    float y2 = fminf(fmaxf(__fadd_rn(pcy, __fmul_rn(0.5f, phd)), 0.0f), maxy);

    // order-preserving transform of float score to uint (ascending)
    unsigned sb  = __float_as_uint(sc);
    unsigned ord = sb ^ (((unsigned)((int)sb >> 31)) | 0x80000000u);

    // reference flat index: i_ref = hw*A + a  (tie-break: smaller index first)
    unsigned iref = (unsigned)(hw * NANCH + a);
    unsigned long long key =
        ((unsigned long long)ord << 32) | (unsigned)(~iref);

    int st = b * NPROP + a * HWSZ + hw;    // coalesced store layout
    g_keys[st]  = key;
    g_boxes[st] = make_float4(x1, y1, x2, y2);
}

// =====================================================================
// Kernel 2: per-batch radix-select top-6000 -> SMEM bitonic sort ->
//           greedy NMS (early exit at 300 kept) -> write output rows
// =====================================================================
__global__ void __launch_bounds__(1024, 1)
topk_nms_kernel(float* __restrict__ out)
{
    extern __shared__ unsigned char smem_raw[];
    SmemLayout& s = *reinterpret_cast<SmemLayout*>(smem_raw);
    const int tid = threadIdx.x;
    const int nt  = 1024;
    const int b   = blockIdx.x;
    const unsigned long long* keys = g_keys + (size_t)b * NPROP;

    // ---- 4-pass radix select: V = score-key of the 6000th-largest ----
    unsigned prefix = 0, prefmask = 0;
    int k = PRE_K;
    for (int p = 24; p >= 0; p -= 8) {
        for (int i0 = tid; i0 < 256; i0 += nt) s.hist[i0] = 0;
        __syncthreads();
        for (int c = tid; c < NPROP; c += nt) {
            unsigned hi = (unsigned)(keys[c] >> 32);
            if ((hi & prefmask) == prefix)
                atomicAdd(&s.hist[(hi >> p) & 255u], 1u);
        }
        __syncthreads();
        if (tid == 0) {
            int cum = 0, sel = 0, newk = k;
            for (int bkt = 255; bkt >= 0; --bkt) {
                int c2 = cum + (int)s.hist[bkt];
                if (c2 >= k) { sel = bkt; newk = k - cum; break; }
                cum = c2;
            }
            s.counters[0] = sel;
            s.counters[1] = newk;
        }
        __syncthreads();
        int sel = s.counters[0];
        k = s.counters[1];
        prefix   |= ((unsigned)sel) << p;
        prefmask |= 0xFFu << p;
        __syncthreads();                  // hist reused next pass
    }
    const unsigned V = prefix;            // exact 32-bit threshold key

    // ---- compact all candidates with score-key >= V into SMEM ----
    if (tid == 0) s.counters[2] = 0;
    for (int i0 = tid; i0 < SORTN; i0 += nt) s.skeys[i0] = 0ull;  // pad = -inf
    __syncthreads();
    for (int c = tid; c < NPROP; c += nt) {
        unsigned long long kk = keys[c];
        if ((unsigned)(kk >> 32) >= V) {
            int slot = atomicAdd(&s.counters[2], 1);
            if (slot < SORTN) s.skeys[slot] = kk;
        }
    }
    __syncthreads();

    // ---- bitonic sort, descending (64-bit key: score desc, index asc) ----
    for (int size = 2; size <= SORTN; size <<= 1) {
        for (int stride = size >> 1; stride > 0; stride >>= 1) {
            for (int t = tid; t < SORTN / 2; t += nt) {
                int i = 2 * t - (t & (stride - 1));
                int j = i + stride;
                bool desc = ((i & size) == 0);
                unsigned long long x = s.skeys[i], y = s.skeys[j];
                if ((x < y) == desc) { s.skeys[i] = y; s.skeys[j] = x; }
            }
            __syncthreads();
        }
    }

    // ---- gather top-6000 boxes into SMEM ----
    for (int r0 = tid; r0 < PRE_K; r0 += nt) {
        unsigned long long kk = s.skeys[r0];
        unsigned iref = ~((unsigned)kk);
        unsigned aa = iref % NANCH;
        unsigned hw = iref / NANCH;
        s.boxes[r0] = g_boxes[(size_t)b * NPROP + aa * HWSZ + hw];
        s.alive[r0] = 1;
    }
    if (tid == 0) s.cur = 0;
    __syncthreads();

    // ---- greedy NMS, early exit at POST_K kept ----
    float* outp = out + (size_t)b * POST_K * 5;
    int kept = 0;
    while (true) {
        // warp 0: ballot-scan for next alive candidate
        if (tid < 32) {
            int c = s.cur;
            int found = -1;
            while (c < PRE_K) {
                int j = c + tid;
                bool al = (j < PRE_K) && (s.alive[j] != 0);
                unsigned m = __ballot_sync(0xffffffffu, al);
                if (m) { found = c + __ffs(m) - 1; break; }
                c += 32;
            }
            if (tid == 0) s.cur = (found < 0) ? PRE_K : found;
        }
        __syncthreads();
        int i = s.cur;
        if (i >= PRE_K) break;

        float4 bi = s.boxes[i];
        if (tid == 0) {
            outp[kept * 5 + 0] = (float)b;
            outp[kept * 5 + 1] = bi.x;
            outp[kept * 5 + 2] = bi.y;
            outp[kept * 5 + 3] = bi.z;
            outp[kept * 5 + 4] = bi.w;
            s.cur = i + 1;
        }
        kept++;
        if (kept >= POST_K) break;

        float areai = __fmul_rn(__fadd_rn(__fsub_rn(bi.z, bi.x), 1.0f),
                                __fadd_rn(__fsub_rn(bi.w, bi.y), 1.0f));
        for (int j = i + 1 + tid; j < PRE_K; j += nt) {
            if (!s.alive[j]) continue;
            float4 bj = s.boxes[j];
            float iw = __fadd_rn(__fsub_rn(fminf(bi.z, bj.z),
                                           fmaxf(bi.x, bj.x)), 1.0f);
            float ih = __fadd_rn(__fsub_rn(fminf(bi.w, bj.w),
                                           fmaxf(bi.y, bj.y)), 1.0f);
            iw = fmaxf(iw, 0.0f);
            ih = fmaxf(ih, 0.0f);
            float inter = __fmul_rn(iw, ih);
            float areaj = __fmul_rn(__fadd_rn(__fsub_rn(bj.z, bj.x), 1.0f),
                                    __fadd_rn(__fsub_rn(bj.w, bj.y), 1.0f));
            float denom = __fsub_rn(__fadd_rn(areai, areaj), inter);
            float iou   = __fdiv_rn(inter, denom);
            if (iou > NMS_T) s.alive[j] = 0;
        }
        __syncthreads();
    }

    // fill remaining rows: (b, 0, 0, 0, 0)
    for (int r0 = kept + tid; r0 < POST_K; r0 += nt) {
        outp[r0 * 5 + 0] = (float)b;
        outp[r0 * 5 + 1] = 0.0f;
        outp[r0 * 5 + 2] = 0.0f;
        outp[r0 * 5 + 3] = 0.0f;
        outp[r0 * 5 + 4] = 0.0f;
    }
}

// =====================================================================
extern "C" void kernel_launch(void* const* d_in, const int* in_sizes, int n_in,
                              void* d_out, int out_size)
{
    const float*    scores  = (const float*)d_in[0];
    const float*    deltas  = (const float*)d_in[1];
    const float*    anchors = (const float*)d_in[2];
    const unsigned* imw     = (const unsigned*)d_in[3];
    const unsigned* imh     = (const unsigned*)d_in[4];
    float*          out     = (float*)d_out;

    const int total  = NBATCH * NPROP;
    const int threads = 256;
    proposal_decode_kernel<<<(total + threads - 1) / threads, threads>>>(
        scores, deltas, anchors, imw, imh);

    cudaFuncSetAttribute(topk_nms_kernel,
                         cudaFuncAttributeMaxDynamicSharedMemorySize,
                         (int)sizeof(SmemLayout));
    topk_nms_kernel<<<NBATCH, 1024, sizeof(SmemLayout)>>>(out);
}

// round 17
// speedup vs baseline: 1.0024x; 1.0024x over previous
#include <cuda_runtime.h>

#define NBATCH   8
#define NANCH    9
#define DIMH     64
#define DIMW     64
#define HWSZ     (DIMH * DIMW)          // 4096
#define NPROP    (NANCH * HWSZ)         // 36864 candidates per batch
#define PRE_K    6000
#define POST_K   300
#define SORTN    8192                   // pow2 >= PRE_K (+ tie slack)
#define NMS_T    0.7f

// ---------------- global scratch (static, allocation-free) ----------------
__device__ unsigned long long g_keys[NBATCH * NPROP];   // (ord_score<<32)|~iref
__device__ float4             g_boxes[NBATCH * NPROP];  // decoded proposals

// ---------------- shared memory layout for kernel 2 ----------------
struct SmemLayout {
    float4             boxes[PRE_K];      // 96000 B
    unsigned long long skeys[SORTN];      // 65536 B
    unsigned int       hist[256];         //  1024 B
    int                counters[4];
    int                cur;
    unsigned char      alive[PRE_K];      //  6000 B
};                                        // ~168.6 KB total

// image_width / image_height may arrive as int32/int64 or float32; decode both.
__device__ __forceinline__ float decode_dim(unsigned u) {
    float f = __uint_as_float(u);
    return (f >= 1.0f && f <= 1.0e7f) ? f : (float)(int)u;
}

// =====================================================================
// Kernel 1: decode proposals + build sort keys (coalesced in (a, hw))
// =====================================================================
__global__ void __launch_bounds__(256)
proposal_decode_kernel(const float* __restrict__ scores,
                       const float* __restrict__ deltas,
                       const float* __restrict__ anchors,
                       const unsigned* __restrict__ pw,
                       const unsigned* __restrict__ ph)
{
    int g = blockIdx.x * blockDim.x + threadIdx.x;
    if (g >= NBATCH * NPROP) return;
    int b  = g / NPROP;
    int r  = g - b * NPROP;
    int a  = r / HWSZ;
    int hw = r - a * HWSZ;
    int h  = hw >> 6;
    int w  = hw & 63;

    float maxx = decode_dim(pw[0]) - 1.0f;   // 1023
    float maxy = decode_dim(ph[0]) - 1.0f;

    // fg score: scores[b, A+a, h, w]
    float sc = scores[(size_t)(b * (2 * NANCH) + NANCH + a) * HWSZ + hw];

    // deltas: bbox_deltas[b, 4a+k, h, w]
    const float* dp = deltas + (size_t)(b * (4 * NANCH) + 4 * a) * HWSZ + hw;
    float d0 = dp[0], d1 = dp[HWSZ], d2 = dp[2 * HWSZ], d3 = dp[3 * HWSZ];

    // shifted anchor
    float sx = (float)(w * 16), sy = (float)(h * 16);
    float a0 = __fadd_rn(anchors[a * 4 + 0], sx);
    float a1 = __fadd_rn(anchors[a * 4 + 1], sy);
    float a2 = __fadd_rn(anchors[a * 4 + 2], sx);
    float a3 = __fadd_rn(anchors[a * 4 + 3], sy);

    // explicit _rn ops: defeat FMA contraction / fast-math to match XLA
    float aw  = __fadd_rn(__fsub_rn(a2, a0), 1.0f);
    float ah  = __fadd_rn(__fsub_rn(a3, a1), 1.0f);
    float acx = __fadd_rn(a0, __fmul_rn(0.5f, aw));
    float acy = __fadd_rn(a1, __fmul_rn(0.5f, ah));
    float pcx = __fadd_rn(__fmul_rn(d0, aw), acx);
    float pcy = __fadd_rn(__fmul_rn(d1, ah), acy);
    float pwd = __fmul_rn(expf(d2), aw);
    float phd = __fmul_rn(expf(d3), ah);

    float x1 = fminf(fmaxf(__fsub_rn(pcx, __fmul_rn(0.5f, pwd)), 0.0f), maxx);
    float y1 = fminf(fmaxf(__fsub_rn(pcy, __fmul_rn(0.5f, phd)), 0.0f), maxy);
    float x2 = fminf(fmaxf(__fadd_rn(pcx, __fmul_rn(0.5f, pwd)), 0.0f), maxx);
    float y2 = fminf(fmaxf(__fadd_rn(pcy, __fmul_rn(0.5f, phd)), 0.0f), maxy);

    // order-preserving transform of float score to uint (ascending)
    unsigned sb  = __float_as_uint(sc);
    unsigned ord = sb ^ (((unsigned)((int)sb >> 31)) | 0x80000000u);

    // reference flat index: i_ref = hw*A + a  (tie-break: smaller index first)
    unsigned iref = (unsigned)(hw * NANCH + a);
    unsigned long long key =
        ((unsigned long long)ord << 32) | (unsigned)(~iref);

    int st = b * NPROP + a * HWSZ + hw;    // coalesced store layout
    g_keys[st]  = key;
    g_boxes[st] = make_float4(x1, y1, x2, y2);
}

// =====================================================================
// Kernel 2: per-batch radix-select top-6000 -> SMEM bitonic sort ->
//           greedy NMS (early exit at 300 kept) -> write output rows
// =====================================================================
__global__ void __launch_bounds__(1024, 1)
topk_nms_kernel(float* __restrict__ out)
{
    extern __shared__ unsigned char smem_raw[];
    SmemLayout& s = *reinterpret_cast<SmemLayout*>(smem_raw);
    const int tid = threadIdx.x;
    const int nt  = 1024;
    const int b   = blockIdx.x;
    const unsigned long long* keys = g_keys + (size_t)b * NPROP;

    // ---- 4-pass radix select: V = score-key of the 6000th-largest ----
    unsigned prefix = 0, prefmask = 0;
    int k = PRE_K;
    for (int p = 24; p >= 0; p -= 8) {
        for (int i0 = tid; i0 < 256; i0 += nt) s.hist[i0] = 0;
        __syncthreads();
        for (int c = tid; c < NPROP; c += nt) {
            unsigned hi = (unsigned)(keys[c] >> 32);
            if ((hi & prefmask) == prefix)
                atomicAdd(&s.hist[(hi >> p) & 255u], 1u);
        }
        __syncthreads();
        if (tid == 0) {
            int cum = 0, sel = 0, newk = k;
            for (int bkt = 255; bkt >= 0; --bkt) {
                int c2 = cum + (int)s.hist[bkt];
                if (c2 >= k) { sel = bkt; newk = k - cum; break; }
                cum = c2;
            }
            s.counters[0] = sel;
            s.counters[1] = newk;
        }
        __syncthreads();
        int sel = s.counters[0];
        k = s.counters[1];
        prefix   |= ((unsigned)sel) << p;
        prefmask |= 0xFFu << p;
        __syncthreads();                  // hist reused next pass
    }
    const unsigned V = prefix;            // exact 32-bit threshold key

    // ---- compact all candidates with score-key >= V into SMEM ----
    if (tid == 0) s.counters[2] = 0;
    for (int i0 = tid; i0 < SORTN; i0 += nt) s.skeys[i0] = 0ull;  // pad = -inf
    __syncthreads();
    for (int c = tid; c < NPROP; c += nt) {
        unsigned long long kk = keys[c];
        if ((unsigned)(kk >> 32) >= V) {
            int slot = atomicAdd(&s.counters[2], 1);
            if (slot < SORTN) s.skeys[slot] = kk;
        }
    }
    __syncthreads();

    // ---- bitonic sort, descending (64-bit key: score desc, index asc) ----
    for (int size = 2; size <= SORTN; size <<= 1) {
        for (int stride = size >> 1; stride > 0; stride >>= 1) {
            for (int t = tid; t < SORTN / 2; t += nt) {
                int i = 2 * t - (t & (stride - 1));
                int j = i + stride;
                bool desc = ((i & size) == 0);
                unsigned long long x = s.skeys[i], y = s.skeys[j];
                if ((x < y) == desc) { s.skeys[i] = y; s.skeys[j] = x; }
            }
            __syncthreads();
        }
    }

    // ---- gather top-6000 boxes into SMEM ----
    for (int r0 = tid; r0 < PRE_K; r0 += nt) {
        unsigned long long kk = s.skeys[r0];
        unsigned iref = ~((unsigned)kk);
        unsigned aa = iref % NANCH;
        unsigned hw = iref / NANCH;
        s.boxes[r0] = g_boxes[(size_t)b * NPROP + aa * HWSZ + hw];
        s.alive[r0] = 1;
    }
    if (tid == 0) s.cur = 0;
    __syncthreads();

    // ---- greedy NMS, early exit at POST_K kept ----
    float* outp = out + (size_t)b * POST_K * 5;
    int kept = 0;
    while (true) {
        // warp 0: ballot-scan for next alive candidate
        if (tid < 32) {
            int c = s.cur;
            int found = -1;
            while (c < PRE_K) {
                int j = c + tid;
                bool al = (j < PRE_K) && (s.alive[j] != 0);
                unsigned m = __ballot_sync(0xffffffffu, al);
                if (m) { found = c + __ffs(m) - 1; break; }
                c += 32;
            }
            if (tid == 0) s.cur = (found < 0) ? PRE_K : found;
        }
        __syncthreads();
        int i = s.cur;
        if (i >= PRE_K) break;

        float4 bi = s.boxes[i];
        if (tid == 0) {
            outp[kept * 5 + 0] = (float)b;
            outp[kept * 5 + 1] = bi.x;
            outp[kept * 5 + 2] = bi.y;
            outp[kept * 5 + 3] = bi.z;
            outp[kept * 5 + 4] = bi.w;
            s.cur = i + 1;
        }
        kept++;
        if (kept >= POST_K) break;

        float areai = __fmul_rn(__fadd_rn(__fsub_rn(bi.z, bi.x), 1.0f),
                                __fadd_rn(__fsub_rn(bi.w, bi.y), 1.0f));
        for (int j = i + 1 + tid; j < PRE_K; j += nt) {
            if (!s.alive[j]) continue;
            float4 bj = s.boxes[j];
            float iw = __fadd_rn(__fsub_rn(fminf(bi.z, bj.z),
                                           fmaxf(bi.x, bj.x)), 1.0f);
            float ih = __fadd_rn(__fsub_rn(fminf(bi.w, bj.w),
                                           fmaxf(bi.y, bj.y)), 1.0f);
            iw = fmaxf(iw, 0.0f);
            ih = fmaxf(ih, 0.0f);
            float inter = __fmul_rn(iw, ih);
            float areaj = __fmul_rn(__fadd_rn(__fsub_rn(bj.z, bj.x), 1.0f),
                                    __fadd_rn(__fsub_rn(bj.w, bj.y), 1.0f));
            float denom = __fsub_rn(__fadd_rn(areai, areaj), inter);
            float iou   = __fdiv_rn(inter, denom);
            if (iou > NMS_T) s.alive[j] = 0;
        }
        __syncthreads();
    }

    // fill remaining rows: (b, 0, 0, 0, 0)
    for (int r0 = kept + tid; r0 < POST_K; r0 += nt) {
        outp[r0 * 5 + 0] = (float)b;
        outp[r0 * 5 + 1] = 0.0f;
        outp[r0 * 5 + 2] = 0.0f;
        outp[r0 * 5 + 3] = 0.0f;
        outp[r0 * 5 + 4] = 0.0f;
    }
}

// =====================================================================
extern "C" void kernel_launch(void* const* d_in, const int* in_sizes, int n_in,
                              void* d_out, int out_size)
{
    const float*    scores  = (const float*)d_in[0];
    const float*    deltas  = (const float*)d_in[1];
    const float*    anchors = (const float*)d_in[2];
    const unsigned* imw     = (const unsigned*)d_in[3];
    const unsigned* imh     = (const unsigned*)d_in[4];
    float*          out     = (float*)d_out;

    const int total  = NBATCH * NPROP;
    const int threads = 256;
    proposal_decode_kernel<<<(total + threads - 1) / threads, threads>>>(
        scores, deltas, anchors, imw, imh);

    cudaFuncSetAttribute(topk_nms_kernel,
                         cudaFuncAttributeMaxDynamicSharedMemorySize,
                         (int)sizeof(SmemLayout));
    topk_nms_kernel<<<NBATCH, 1024, sizeof(SmemLayout)>>>(out);
}